// round 9
// baseline (speedup 1.0000x reference)
#include <cuda_runtime.h>
#include <cuda_fp16.h>
#include <math.h>
#include <stdint.h>

#define DIM    64
#define NCODES 1024
#define NROWS  65536
#define HW     4096
#define QELEMS 4194304
#define FULL_OUT 71368706

__device__ float  g_b[NCODES];
__device__ int    g_hist[NCODES];
__device__ double g_loss;
__device__ __align__(16) uint32_t g_eh[NCODES * 32];  // [chunk][dpair][codeL] half2

// ---------------------------------------------------------------------------
__global__ void init_kernel(const float* __restrict__ emb) {
    int t = blockIdx.x * 128 + threadIdx.x;        // code 0..1023
    g_hist[t] = 0;
    if (t == 0) g_loss = 0.0;
    const float4* e4 = (const float4*)(emb + t * DIM);
    float4 v[16];
#pragma unroll
    for (int i = 0; i < 16; ++i) v[i] = e4[i];
    float s = 0.f;
#pragma unroll
    for (int i = 0; i < 16; ++i) {                 // reference rounding chain
        s = __fadd_rn(s, __fmul_rn(v[i].x, v[i].x));
        s = __fadd_rn(s, __fmul_rn(v[i].y, v[i].y));
        s = __fadd_rn(s, __fmul_rn(v[i].z, v[i].z));
        s = __fadd_rn(s, __fmul_rn(v[i].w, v[i].w));
    }
    g_b[t] = s;
    int c = t >> 6, cl = t & 63;                   // half2 codebook, [chunk][dp][codeL]
#pragma unroll
    for (int i = 0; i < 16; ++i) {
        __half2 h0 = __floats2half2_rn(v[i].x, v[i].y);
        __half2 h1 = __floats2half2_rn(v[i].z, v[i].w);
        g_eh[c * 2048 + (2 * i) * 64 + cl]     = *(uint32_t*)&h0;
        g_eh[c * 2048 + (2 * i + 1) * 64 + cl] = *(uint32_t*)&h1;
    }
}

// ---------------------------------------------------------------------------
__global__ void __launch_bounds__(256, 2) vq_kernel(
    const float* __restrict__ xin, const float* __restrict__ emb,
    float* __restrict__ oq, float* __restrict__ oenc, float* __restrict__ oidx)
{
    __shared__ __align__(16) uint32_t Xh[32 * 128];   // 16 KB half2 [dpair][row]
    __shared__ __align__(16) uint32_t Eh[2048];       //  8 KB one E chunk [dpair][codeL]
    __shared__ float s_a[128];
    __shared__ float s_dlt[128];
    __shared__ int   scand[128][16];
    __shared__ int   scnt[128];
    __shared__ int   sidx[128];

    int tid = threadIdx.x;
    int tr  = tid & 31;               // rows tr*4 .. tr*4+3 (warp = fixed tc)
    int tc  = tid >> 5;               // codes tc*8 .. tc*8+7 per chunk
    int n0  = blockIdx.x * 128;
    int img = n0 >> 12, hw0 = n0 & 4095;
    const float* gbase = xin + (size_t)img * (DIM * HW) + hw0;

    // ---- prologue ----
    if (tid < 128) {                  // thread = row: a (exact chain), sa, pack Xh
        int row = tid;
        float a = 0.f, sa = 0.f;
#pragma unroll
        for (int dp = 0; dp < 32; ++dp) {
            float v0 = gbase[(2 * dp) * HW + row];
            float v1 = gbase[(2 * dp + 1) * HW + row];
            a  = __fadd_rn(a, __fmul_rn(v0, v0));
            a  = __fadd_rn(a, __fmul_rn(v1, v1));
            sa += fabsf(v0) + fabsf(v1);
            __half2 h = __floats2half2_rn(v0, v1);
            Xh[dp * 128 + row] = *(uint32_t*)&h;
        }
        s_a[row]   = a;
        s_dlt[row] = __fmaf_rn(sa, 1.6e-4f, 1e-4f);
        scnt[row]  = 0;
    } else {                          // stage E chunk 0
        int t0 = tid - 128;
#pragma unroll
        for (int k = 0; k < 16; ++k) Eh[t0 + k * 128] = g_eh[t0 + k * 128];
    }
    __syncthreads();

    float dlt[4];
#pragma unroll
    for (int rs = 0; rs < 4; ++rs) dlt[rs] = s_dlt[tr * 4 + rs];

    const float INF = __int_as_float(0x7f800000);
    float umin[4], sc[4][4];
    int   cd[4][4];
    bool  ovf[4];
#pragma unroll
    for (int rs = 0; rs < 4; ++rs) {
        umin[rs] = INF; ovf[rs] = false;
#pragma unroll
        for (int j = 0; j < 4; ++j) { sc[rs][j] = INF; cd[rs][j] = 0; }
    }

    // ---- main loop: 16 chunks of 64 codes, fp16 HFMA2 prefilter ----
    for (int c = 0; c < 16; ++c) {
        uint32_t pf[8];
        if (c < 15) {
            const uint32_t* src = g_eh + (c + 1) * 2048;
#pragma unroll
            for (int k = 0; k < 8; ++k) pf[k] = src[tid + k * 256];
        }
        __half2 acc[4][8];
#pragma unroll
        for (int r = 0; r < 4; ++r)
#pragma unroll
            for (int j = 0; j < 8; ++j) acc[r][j] = __floats2half2_rn(0.f, 0.f);

#pragma unroll 8
        for (int dp = 0; dp < 32; ++dp) {
            uint4 xw = *(const uint4*)&Xh[dp * 128 + tr * 4];        // 4 rows
            uint4 e0 = *(const uint4*)&Eh[dp * 64 + tc * 8];         // codes 0-3 (bcast)
            uint4 e1 = *(const uint4*)&Eh[dp * 64 + tc * 8 + 4];     // codes 4-7 (bcast)
            const uint32_t* xp = (const uint32_t*)&xw;
            const uint32_t* ep[2] = { (const uint32_t*)&e0, (const uint32_t*)&e1 };
#pragma unroll
            for (int j = 0; j < 8; ++j) {
                __half2 ev = *(__half2*)&ep[j >> 2][j & 3];
                acc[0][j] = __hfma2(*(__half2*)&xp[0], ev, acc[0][j]);
                acc[1][j] = __hfma2(*(__half2*)&xp[1], ev, acc[1][j]);
                acc[2][j] = __hfma2(*(__half2*)&xp[2], ev, acc[2][j]);
                acc[3][j] = __hfma2(*(__half2*)&xp[3], ev, acc[3][j]);
            }
        }
        __syncthreads();                            // Eh reads done
        if (c < 15) {
#pragma unroll
            for (int k = 0; k < 8; ++k) Eh[tid + k * 256] = pf[k];
        }

        // approx scores u = b - 2m (a omitted: constant per row) + collection
#pragma unroll
        for (int j = 0; j < 8; ++j) {
            int code = c * 64 + tc * 8 + j;
            float bb = __ldg(&g_b[code]);
#pragma unroll
            for (int rs = 0; rs < 4; ++rs) {
                float m = __low2float(acc[rs][j]) + __high2float(acc[rs][j]);
                float u = __fmaf_rn(-2.0f, m, bb);
                if (u < umin[rs] + dlt[rs]) {
                    if (u < umin[rs]) umin[rs] = u;
                    bool ins = false;
#pragma unroll
                    for (int q = 0; q < 4; ++q)
                        if (!ins && sc[rs][q] >= umin[rs] + dlt[rs]) {
                            sc[rs][q] = u; cd[rs][q] = code; ins = true;
                        }
                    if (!ins) ovf[rs] = true;
                }
            }
        }
        __syncthreads();                            // Eh(c+1) staged
    }

    // ---- dump surviving candidates per row ----
#pragma unroll
    for (int rs = 0; rs < 4; ++rs) {
        int row = tr * 4 + rs;
        if (ovf[rs]) atomicAdd(&scnt[row], 1000);   // force full-scan fallback
        else {
#pragma unroll
            for (int q = 0; q < 4; ++q)
                if (sc[rs][q] < umin[rs] + dlt[rs]) {
                    int p = atomicAdd(&scnt[row], 1);
                    if (p < 16) scand[row][p] = cd[rs][q];
                    else        atomicAdd(&scnt[row], 1000);
                }
        }
    }
    __syncthreads();

    // ---- exact rescore, thread = row (bitwise-identical R4 chain) ----
    double lsum = 0.0;
    if (tid < 128) {
        int row = tid;
        float x[DIM];
#pragma unroll
        for (int d = 0; d < DIM; ++d) x[d] = gbase[d * HW + row];   // L2-hot
        float aex = s_a[row];
        int   cnt = scnt[row];
        unsigned long long bestk = 0xFFFFFFFFFFFFFFFFull;
        if (cnt >= 1 && cnt <= 16) {
            for (int q = 0; q < cnt; ++q) {
                int code = scand[row][q];
                const float* e = emb + code * DIM;
                float m = 0.f;
#pragma unroll
                for (int d = 0; d < DIM; ++d) m = __fmaf_rn(x[d], e[d], m);
                float s = __fadd_rn(__fadd_rn(aex, g_b[code]), -2.0f * m);
                unsigned long long key =
                    ((unsigned long long)__float_as_uint(s) << 32) | (unsigned)code;
                if (key < bestk) bestk = key;
            }
        } else {                                    // fallback: full exact scan
            for (int code = 0; code < NCODES; ++code) {
                const float* e = emb + code * DIM;
                float m = 0.f;
#pragma unroll
                for (int d = 0; d < DIM; ++d) m = __fmaf_rn(x[d], e[d], m);
                float s = __fadd_rn(__fadd_rn(aex, g_b[code]), -2.0f * m);
                unsigned long long key =
                    ((unsigned long long)__float_as_uint(s) << 32) | (unsigned)code;
                if (key < bestk) bestk = key;
            }
        }
        int idx = (int)(bestk & 0xFFFFFFFFull);
        sidx[row] = idx;
        atomicAdd(&g_hist[idx], 1);
        if (oidx) oidx[n0 + row] = (float)idx;
        const float* e = emb + idx * DIM;
        float ls = 0.f;
#pragma unroll
        for (int d = 0; d < DIM; ++d) {
            float dif = e[d] - x[d];
            ls = __fmaf_rn(dif, dif, ls);
        }
        lsum = (double)ls;
    }
#pragma unroll
    for (int off = 16; off; off >>= 1)
        lsum += __shfl_down_sync(0xffffffffu, lsum, off);
    if (tid < 128 && (tid & 31) == 0) atomicAdd(&g_loss, lsum);
    __syncthreads();

    // ---- quantized_st, NCHW (coalesced 128-float runs per channel) ----
    for (int i = tid; i < DIM * 128; i += 256) {
        int cc = i >> 7, row = i & 127;
        oq[(size_t)img * (DIM * HW) + cc * HW + hw0 + row] = emb[sidx[row] * DIM + cc];
    }

    // ---- one-hot encodings (base only 8B-aligned -> float2) ----
    if (oenc) {
        float2* enc2 = (float2*)oenc;
        for (int i = tid; i < 128 * 512; i += 256) {
            int row = i >> 9, jj = i & 511;
            int id = sidx[row];
            float2 z = make_float2(0.f, 0.f);
            if ((id >> 1) == jj) ((float*)&z)[id & 1] = 1.0f;
            enc2[(size_t)(n0 + row) * 512 + jj] = z;
        }
    }
}

// ---------------------------------------------------------------------------
__global__ void finalize_kernel(float* __restrict__ oloss, float* __restrict__ operp) {
    int t = threadIdx.x;                            // 1024 threads
    double p = (double)g_hist[t] / 65536.0;
    double h = -p * log(p + 1e-10);
    __shared__ double sh[32];
#pragma unroll
    for (int off = 16; off; off >>= 1) h += __shfl_down_sync(0xffffffffu, h, off);
    if ((t & 31) == 0) sh[t >> 5] = h;
    __syncthreads();
    if (t < 32) {
        double v = sh[t];
#pragma unroll
        for (int off = 16; off; off >>= 1) v += __shfl_down_sync(0xffffffffu, v, off);
        if (t == 0) {
            operp[0] = (float)exp(v);
            oloss[0] = (float)(1.25 * (g_loss / (double)QELEMS));
        }
    }
}

// ---------------------------------------------------------------------------
extern "C" void kernel_launch(void* const* d_in, const int* in_sizes, int n_in,
                              void* d_out, int out_size) {
    const float* xin = (const float*)d_in[0];
    const float* emb = (const float*)d_in[1];
    if (n_in >= 2 && in_sizes[0] == NCODES * DIM && in_sizes[1] == QELEMS) {
        xin = (const float*)d_in[1];
        emb = (const float*)d_in[0];
    }
    float* out  = (float*)d_out;
    bool   full = (out_size >= FULL_OUT);
    float* o_q   = full ? out + 1 : out;
    float* o_enc = full ? out + (size_t)QELEMS + 2 : nullptr;
    float* o_idx = full ? out + (size_t)QELEMS + 2 + (size_t)NROWS * NCODES : nullptr;

    init_kernel<<<8, 128>>>(emb);
    vq_kernel<<<512, 256>>>(xin, emb, o_q, o_enc, o_idx);
    if (full) finalize_kernel<<<1, 1024>>>(out, out + QELEMS + 1);
}

// round 10
// speedup vs baseline: 5.5505x; 5.5505x over previous
#include <cuda_runtime.h>
#include <math.h>
#include <stdint.h>

#define DIM    64
#define NCODES 1024
#define NROWS  65536
#define HW     4096
#define QELEMS 4194304
#define FULL_OUT 71368706

__device__ float  g_b[NCODES];
__device__ int    g_hist[NCODES];
__device__ double g_loss;

// ---------------------------------------------------------------------------
// init: hist/loss zero + b_k = ||e_k||^2 with the reference rounding chain.
// ---------------------------------------------------------------------------
__global__ void init_kernel(const float* __restrict__ emb) {
    int t = blockIdx.x * 128 + threadIdx.x;        // code 0..1023
    g_hist[t] = 0;
    if (t == 0) g_loss = 0.0;
    const float4* e4 = (const float4*)(emb + t * DIM);
    float4 v[16];
#pragma unroll
    for (int i = 0; i < 16; ++i) v[i] = e4[i];
    float s = 0.f;
#pragma unroll
    for (int i = 0; i < 16; ++i) {
        s = __fadd_rn(s, __fmul_rn(v[i].x, v[i].x));
        s = __fadd_rn(s, __fmul_rn(v[i].y, v[i].y));
        s = __fadd_rn(s, __fmul_rn(v[i].z, v[i].z));
        s = __fadd_rn(s, __fmul_rn(v[i].w, v[i].w));
    }
    g_b[t] = s;
}

// ---------------------------------------------------------------------------
// fused exact argmin, 64-row tiles. Thread tile: 2 rows (tr, tr+32) x 8 codes.
// Encodings zero-stores are streamed through the 16 chunks (hidden in FFMA
// issue gaps); only the per-row 1.0 lands in the epilogue.
// ---------------------------------------------------------------------------
__global__ void __launch_bounds__(256, 3) vq_kernel(
    const float* __restrict__ xin, const float* __restrict__ emb,
    float* __restrict__ oq, float* __restrict__ oenc, float* __restrict__ oidx)
{
    __shared__ __align__(16) float Xs[DIM * 64];    // 16 KB fp32 [d][row]
    __shared__ __align__(16) float Es[64 * DIM];    // 16 KB one E chunk [code][d]
    __shared__ unsigned long long keys[64];
    __shared__ int sidx[64];

    int tid = threadIdx.x;
    int tr  = tid & 31;               // rows tr and tr+32
    int tc  = tid >> 5;               // codes tc*8 .. tc*8+7 per chunk (warp-uniform)
    int n0  = blockIdx.x * 64;
    int img = n0 >> 12, hw0 = n0 & 4095;
    const float* gbase = xin + (size_t)img * (DIM * HW) + hw0;

    // stage X tile: NCHW -> smem[d][row], coalesced 256B runs
    for (int i = tid; i < DIM * 64; i += 256) {
        int d = i >> 6, r = i & 63;
        Xs[i] = gbase[d * HW + r];
    }
    if (tid < 64) keys[tid] = 0xFFFFFFFFFFFFFFFFull;
    __syncthreads();

    // exact a per row (reference chain: sequential d, round-mul then round-add)
    int r0 = tr, r1 = tr + 32;
    float a0 = 0.f, a1 = 0.f;
#pragma unroll
    for (int d = 0; d < DIM; ++d) {
        float v0 = Xs[d * 64 + r0], v1 = Xs[d * 64 + r1];
        a0 = __fadd_rn(a0, __fmul_rn(v0, v0));
        a1 = __fadd_rn(a1, __fmul_rn(v1, v1));
    }

    const float INF = __int_as_float(0x7f800000);
    float best0 = INF, best1 = INF;
    int   bix0 = 0, bix1 = 0;

    float2* enc2 = oenc ? (float2*)oenc : nullptr;
    const float2 z2 = make_float2(0.f, 0.f);

    for (int c = 0; c < 16; ++c) {
        // stage E chunk (64 codes x 64 dims fp32)
        {
            const float4* src = (const float4*)(emb + c * (64 * DIM));
            float4* dst = (float4*)Es;
#pragma unroll
            for (int k = 0; k < 4; ++k) dst[tid + k * 256] = src[tid + k * 256];
        }
        // streamed encodings zero-stores: rows n0..n0+63, cols c*64..c*64+63
        if (enc2) {
#pragma unroll
            for (int k = 0; k < 8; ++k) {
                int i = tid + k * 256;             // 0..2047 float2 slots
                int row = i >> 5, cp = i & 31;     // 32 float2 = 64 cols
                enc2[(size_t)(n0 + row) * 512 + c * 32 + cp] = z2;
            }
        }
        __syncthreads();

        float acc0[8], acc1[8];
#pragma unroll
        for (int j = 0; j < 8; ++j) { acc0[j] = 0.f; acc1[j] = 0.f; }

#pragma unroll 4
        for (int dk = 0; dk < DIM; dk += 4) {
            float4 e4[8];
#pragma unroll
            for (int j = 0; j < 8; ++j)           // warp-uniform -> broadcast
                e4[j] = *(const float4*)&Es[(tc * 8 + j) * DIM + dk];
#pragma unroll
            for (int t = 0; t < 4; ++t) {
                float x0 = Xs[(dk + t) * 64 + r0];  // lane=row: conflict-free
                float x1 = Xs[(dk + t) * 64 + r1];
#pragma unroll
                for (int j = 0; j < 8; ++j) {
                    float ev = ((const float*)&e4[j])[t];
                    acc0[j] = __fmaf_rn(x0, ev, acc0[j]);
                    acc1[j] = __fmaf_rn(x1, ev, acc1[j]);
                }
            }
        }

        // score s = round((a+b) - 2m): fma(-2, m, ab) == fadd(fadd(a,b), -2m)
        // (-2m exact, single rounding either way). Strict < + ascending codes
        // == first-occurrence argmin.
#pragma unroll
        for (int j = 0; j < 8; ++j) {
            int code = c * 64 + tc * 8 + j;
            float bb = __ldg(&g_b[code]);
            float s0 = __fmaf_rn(-2.0f, acc0[j], __fadd_rn(a0, bb));
            float s1 = __fmaf_rn(-2.0f, acc1[j], __fadd_rn(a1, bb));
            if (s0 < best0) { best0 = s0; bix0 = code; }
            if (s1 < best1) { best1 = s1; bix1 = code; }
        }
        __syncthreads();                           // Es reads done before restage
    }

    // cross-thread row argmin: packed (score_bits<<32)|code, atomicMin.
    // Scores >0 -> fp32 bits order-preserving; ties -> smaller code wins.
    atomicMin(&keys[r0], ((unsigned long long)__float_as_uint(best0) << 32) | (unsigned)bix0);
    atomicMin(&keys[r1], ((unsigned long long)__float_as_uint(best1) << 32) | (unsigned)bix1);
    __syncthreads();

    double lsum = 0.0;
    if (tid < 64) {
        int idx = (int)(keys[tid] & 0xFFFFFFFFull);
        sidx[tid] = idx;
        atomicAdd(&g_hist[idx], 1);
        if (oidx) oidx[n0 + tid] = (float)idx;
        const float* e = emb + idx * DIM;
        float ls = 0.f;
#pragma unroll
        for (int d = 0; d < DIM; ++d) {
            float dif = e[d] - Xs[d * 64 + tid];
            ls = __fmaf_rn(dif, dif, ls);
        }
        lsum = (double)ls;
    }
#pragma unroll
    for (int off = 16; off; off >>= 1)
        lsum += __shfl_down_sync(0xffffffffu, lsum, off);
    if (tid < 64 && (tid & 31) == 0) atomicAdd(&g_loss, lsum);
    __syncthreads();

    // quantized_st, NCHW: 64-float (256B) coalesced runs per channel
    for (int i = tid; i < DIM * 64; i += 256) {
        int cc = i >> 6, row = i & 63;
        oq[(size_t)img * (DIM * HW) + cc * HW + hw0 + row] = emb[sidx[row] * DIM + cc];
    }

    // the single 1.0 per row (zeros already written during the mainloop;
    // ordering guaranteed by the __syncthreads() between the stores)
    if (oenc && tid < 64)
        oenc[(size_t)(n0 + tid) * NCODES + sidx[tid]] = 1.0f;
}

// ---------------------------------------------------------------------------
__global__ void finalize_kernel(float* __restrict__ oloss, float* __restrict__ operp) {
    int t = threadIdx.x;                           // 1024 threads
    double p = (double)g_hist[t] / 65536.0;
    double h = -p * log(p + 1e-10);
    __shared__ double sh[32];
#pragma unroll
    for (int off = 16; off; off >>= 1) h += __shfl_down_sync(0xffffffffu, h, off);
    if ((t & 31) == 0) sh[t >> 5] = h;
    __syncthreads();
    if (t < 32) {
        double v = sh[t];
#pragma unroll
        for (int off = 16; off; off >>= 1) v += __shfl_down_sync(0xffffffffu, v, off);
        if (t == 0) {
            operp[0] = (float)exp(v);
            oloss[0] = (float)(1.25 * (g_loss / (double)QELEMS));
        }
    }
}

// ---------------------------------------------------------------------------
extern "C" void kernel_launch(void* const* d_in, const int* in_sizes, int n_in,
                              void* d_out, int out_size) {
    const float* xin = (const float*)d_in[0];
    const float* emb = (const float*)d_in[1];
    if (n_in >= 2 && in_sizes[0] == NCODES * DIM && in_sizes[1] == QELEMS) {
        xin = (const float*)d_in[1];
        emb = (const float*)d_in[0];
    }
    float* out  = (float*)d_out;
    bool   full = (out_size >= FULL_OUT);
    float* o_q   = full ? out + 1 : out;
    float* o_enc = full ? out + (size_t)QELEMS + 2 : nullptr;
    float* o_idx = full ? out + (size_t)QELEMS + 2 + (size_t)NROWS * NCODES : nullptr;

    init_kernel<<<8, 128>>>(emb);
    vq_kernel<<<1024, 256>>>(xin, emb, o_q, o_enc, o_idx);
    if (full) finalize_kernel<<<1, 1024>>>(out, out + QELEMS + 1);
}